// round 6
// baseline (speedup 1.0000x reference)
#include <cuda_runtime.h>
#include <cuda_fp16.h>
#include <math.h>
#include <stdint.h>

#define DIMX 1024
#define COND_DIM 512
#define HEADS 32
#define DIM_HEAD 32
#define NTOK 65
#define B_TOT 512
#define B_IMG 16
#define M_TOK (B_TOT * NTOK)
#define TWO_DIM (2 * DIMX)

__device__ float  g_gb[B_IMG * TWO_DIM];
__device__ __half g_xnh[(size_t)M_TOK * DIMX];
__device__ float  g_qkv[(size_t)M_TOK * 3 * DIMX];
__device__ __half g_oh[(size_t)M_TOK * DIMX];
__device__ __half g_wqkvT[(size_t)3 * DIMX * DIMX];
__device__ __half g_woutT[(size_t)DIMX * DIMX];

#define CPA16(d, s) asm volatile("cp.async.cg.shared.global [%0], [%1], 16;" :: "r"(d), "l"(s) : "memory")
#define CPC()   asm volatile("cp.async.commit_group;" ::: "memory")
#define CPW0()  asm volatile("cp.async.wait_group 0;" ::: "memory")
#define CPW1()  asm volatile("cp.async.wait_group 1;" ::: "memory")

__device__ __forceinline__ uint32_t smem_u32(const void* p) {
    uint32_t a; asm("{ .reg .u64 t; cvta.to.shared.u64 t, %1; cvt.u32.u64 %0, t; }" : "=r"(a) : "l"(p));
    return a;
}
__device__ __forceinline__ void mma_f16(float* d, const uint32_t* a, const uint32_t* b) {
    asm volatile(
        "mma.sync.aligned.m16n8k16.row.col.f32.f16.f16.f32 "
        "{%0,%1,%2,%3}, {%4,%5,%6,%7}, {%8,%9}, {%0,%1,%2,%3};\n"
        : "+f"(d[0]), "+f"(d[1]), "+f"(d[2]), "+f"(d[3])
        : "r"(a[0]), "r"(a[1]), "r"(a[2]), "r"(a[3]), "r"(b[0]), "r"(b[1]));
}

// ---- fused FiLM MLP: one block per image ----
__global__ __launch_bounds__(256) void film_fused_kernel(
    const float* __restrict__ cond, const float* __restrict__ w1, const float* __restrict__ b1,
    const float* __restrict__ w2, const float* __restrict__ b2)
{
    __shared__ float cs[COND_DIM];
    __shared__ float hs[TWO_DIM];
    const int i = blockIdx.x, t = threadIdx.x;
    for (int k = t; k < COND_DIM; k += 256) cs[k] = cond[i * COND_DIM + k];
    __syncthreads();
    float acc[8];
    #pragma unroll
    for (int p = 0; p < 8; p++) acc[p] = b1[t + p * 256];
    for (int k = 0; k < COND_DIM; k++) {
        float c = cs[k];
        const float* wr = w1 + (size_t)k * TWO_DIM + t;
        #pragma unroll
        for (int p = 0; p < 8; p++) acc[p] = fmaf(c, wr[p * 256], acc[p]);
    }
    #pragma unroll
    for (int p = 0; p < 8; p++) hs[t + p * 256] = acc[p] / (1.f + __expf(-acc[p]));
    __syncthreads();
    #pragma unroll
    for (int p = 0; p < 8; p++) acc[p] = b2[t + p * 256];
    for (int k = 0; k < TWO_DIM; k++) {
        float c = hs[k];
        const float* wr = w2 + (size_t)k * TWO_DIM + t;
        #pragma unroll
        for (int p = 0; p < 8; p++) acc[p] = fmaf(c, wr[p * 256], acc[p]);
    }
    #pragma unroll
    for (int p = 0; p < 8; p++) g_gb[i * TWO_DIM + t + p * 256] = acc[p];
}

// ---- fused weight transpose: W[K][N] f32 -> WT[N][K] half (both weights) ----
__global__ __launch_bounds__(256) void wtrans_kernel(
    const float* __restrict__ Wq, const float* __restrict__ Wo)
{
    __shared__ float tbuf[32][33];
    int tx = threadIdx.x & 31, ty = threadIdx.x >> 5;
    const float* W;
    __half* WT;
    int N, n0;
    if (blockIdx.x < 96) { W = Wq; WT = g_wqkvT; N = 3 * DIMX; n0 = blockIdx.x * 32; }
    else                 { W = Wo; WT = g_woutT; N = DIMX;     n0 = (blockIdx.x - 96) * 32; }
    int k0 = blockIdx.y * 32;
    #pragma unroll
    for (int r = 0; r < 32; r += 8)
        tbuf[ty + r][tx] = W[(size_t)(k0 + ty + r) * N + n0 + tx];
    __syncthreads();
    #pragma unroll
    for (int r = 0; r < 32; r += 8)
        WT[(size_t)(n0 + ty + r) * DIMX + k0 + tx] = __float2half_rn(tbuf[tx][ty + r]);
}

// ---- LayerNorm + FiLM -> half ----
__global__ __launch_bounds__(256) void ln_film_kernel(const float* __restrict__ x)
{
    int row = blockIdx.x;
    int img = (row / NTOK) >> 5;
    const float4* xr = (const float4*)(x + (size_t)row * DIMX);
    int t = threadIdx.x;
    float4 v = xr[t];
    float s = v.x + v.y + v.z + v.w;
    float ss = v.x*v.x + v.y*v.y + v.z*v.z + v.w*v.w;
    __shared__ float rs_[8], rss[8];
    #pragma unroll
    for (int o = 16; o > 0; o >>= 1) {
        s += __shfl_down_sync(~0u, s, o); ss += __shfl_down_sync(~0u, ss, o);
    }
    int warp = t >> 5, lane = t & 31;
    if (lane == 0) { rs_[warp] = s; rss[warp] = ss; }
    __syncthreads();
    if (warp == 0) {
        s = (lane < 8) ? rs_[lane] : 0.f; ss = (lane < 8) ? rss[lane] : 0.f;
        #pragma unroll
        for (int o = 4; o > 0; o >>= 1) {
            s += __shfl_down_sync(~0u, s, o); ss += __shfl_down_sync(~0u, ss, o);
        }
        if (lane == 0) { rs_[0] = s; rss[0] = ss; }
    }
    __syncthreads();
    float mu = rs_[0] * (1.f / DIMX);
    float var = rss[0] * (1.f / DIMX) - mu * mu;
    float rstd = rsqrtf(var + 1e-5f);
    const float4* gam = (const float4*)(g_gb + (size_t)img * TWO_DIM);
    const float4* bet = (const float4*)(g_gb + (size_t)img * TWO_DIM + DIMX);
    float4 gv = gam[t], bv = bet[t];
    __half2 h0 = __floats2half2_rn(fmaf((v.x - mu) * rstd, gv.x, bv.x),
                                   fmaf((v.y - mu) * rstd, gv.y, bv.y));
    __half2 h1 = __floats2half2_rn(fmaf((v.z - mu) * rstd, gv.z, bv.z),
                                   fmaf((v.w - mu) * rstd, gv.w, bv.w));
    ((__half2*)(g_xnh + (size_t)row * DIMX))[t * 2]     = h0;
    ((__half2*)(g_xnh + (size_t)row * DIMX))[t * 2 + 1] = h1;
}

// ---- fp16 GEMM: C[M,N] f32 = A[M,K]h @ Bt[N,K]h^T. 128x128x32 tile, 8 warps 64x32,
//      4-stage cp.async. ASTR=40 halves/row, padded: conflict-free frag LDS. ----
#define ASTR 40
#define TILE_B (128 * ASTR * 2)       // 10240 per operand
#define STG_B (2 * TILE_B)            // 20480 per stage
#define HG_SMEM (4 * STG_B)           // 81920

__global__ __launch_bounds__(256, 2) void hgemm_kernel(
    const __half* __restrict__ A, const __half* __restrict__ Bt,
    float* __restrict__ C, int N, int K)
{
    extern __shared__ char sm[];
    const uint32_t sb = smem_u32(sm);
    const int tid = threadIdx.x, warp = tid >> 5, lane = tid & 31;
    const int g = lane >> 2, tig = lane & 3;
    const int wm = (warp & 1) * 64, wn = (warp >> 1) * 32;
    const int row0 = blockIdx.y * 128, col0 = blockIdx.x * 128;

    float acc[4][4][4];
    #pragma unroll
    for (int mi = 0; mi < 4; mi++)
        #pragma unroll
        for (int nj = 0; nj < 4; nj++)
            #pragma unroll
            for (int c = 0; c < 4; c++) acc[mi][nj][c] = 0.f;

    const int l_row = tid >> 1;                 // 0..127
    const int l_kc0 = (tid & 1) * 2;            // 0 or 2 (2 chunks of 16B each)
    const __half* Ag = A + (size_t)(row0 + l_row) * K + l_kc0 * 8;
    const __half* Bg = Bt + (size_t)(col0 + l_row) * K + l_kc0 * 8;
    const uint32_t sAd = sb + l_row * 80 + l_kc0 * 16;
    const uint32_t sBd = sAd + TILE_B;

    const int KITERS = K >> 5;
    #pragma unroll
    for (int s = 0; s < 2; s++) {
        #pragma unroll
        for (int p = 0; p < 2; p++) {
            CPA16(sAd + s * STG_B + p * 16, Ag + s * 32 + p * 8);
            CPA16(sBd + s * STG_B + p * 16, Bg + s * 32 + p * 8);
        }
        CPC();
    }
    for (int kt = 0; kt < KITERS; kt++) {
        if (kt >= KITERS - 2) { CPW0(); } else { CPW1(); }
        __syncthreads();
        if (kt + 2 < KITERS) {
            const int s = (kt + 2) & 3;
            const int k0 = (kt + 2) << 5;
            #pragma unroll
            for (int p = 0; p < 2; p++) {
                CPA16(sAd + s * STG_B + p * 16, Ag + k0 + p * 8);
                CPA16(sBd + s * STG_B + p * 16, Bg + k0 + p * 8);
            }
            CPC();
        }
        const uint32_t* swA = (const uint32_t*)(sm + (kt & 3) * STG_B);
        const uint32_t* swB = (const uint32_t*)(sm + (kt & 3) * STG_B + TILE_B);
        #pragma unroll
        for (int kk = 0; kk < 2; kk++) {
            uint32_t af[4][4], bf[4][2];
            const int kw = kk * 8 + tig;
            #pragma unroll
            for (int mi = 0; mi < 4; mi++) {
                int m = wm + mi * 16 + g;
                af[mi][0] = swA[m * 20 + kw];
                af[mi][1] = swA[(m + 8) * 20 + kw];
                af[mi][2] = swA[m * 20 + kw + 4];
                af[mi][3] = swA[(m + 8) * 20 + kw + 4];
            }
            #pragma unroll
            for (int nj = 0; nj < 4; nj++) {
                int n = wn + nj * 8 + g;
                bf[nj][0] = swB[n * 20 + kw];
                bf[nj][1] = swB[n * 20 + kw + 4];
            }
            #pragma unroll
            for (int mi = 0; mi < 4; mi++)
                #pragma unroll
                for (int nj = 0; nj < 4; nj++)
                    mma_f16(acc[mi][nj], af[mi], bf[nj]);
        }
        __syncthreads();
    }
    #pragma unroll
    for (int mi = 0; mi < 4; mi++) {
        #pragma unroll
        for (int nj = 0; nj < 4; nj++) {
            int r = row0 + wm + mi * 16 + g;
            int c = col0 + wn + nj * 8 + tig * 2;
            *(float2*)(C + (size_t)r * N + c)       = make_float2(acc[mi][nj][0], acc[mi][nj][1]);
            *(float2*)(C + (size_t)(r + 8) * N + c) = make_float2(acc[mi][nj][2], acc[mi][nj][3]);
        }
    }
}

// ---- attention ----
__global__ __launch_bounds__(256) void attn_kernel(
    const float* __restrict__ q_gamma, const float* __restrict__ k_gamma,
    const float* __restrict__ rel_emb, const int* __restrict__ rel_idx)
{
    int b = blockIdx.x, h = blockIdx.y;
    __shared__ float qs[NTOK][DIM_HEAD], ks[NTOK][DIM_HEAD], vs[NTOK][DIM_HEAD];
    __shared__ float ps[NTOK][NTOK + 1], qg[DIM_HEAD], kg[DIM_HEAD];
    int t = threadIdx.x;
    if (t < DIM_HEAD) { qg[t] = q_gamma[h * DIM_HEAD + t]; kg[t] = k_gamma[h * DIM_HEAD + t]; }
    const float* base = g_qkv + (size_t)(b * NTOK) * (3 * DIMX) + h * DIM_HEAD;
    for (int e = t; e < NTOK * DIM_HEAD; e += 256) {
        int n = e >> 5, d = e & 31;
        const float* r = base + (size_t)n * (3 * DIMX);
        qs[n][d] = r[d]; ks[n][d] = r[DIMX + d]; vs[n][d] = r[2 * DIMX + d];
    }
    __syncthreads();
    if (t < NTOK) {
        float ss = 0.f;
        #pragma unroll
        for (int d = 0; d < DIM_HEAD; d++) { float v = qs[t][d]; ss += v * v; }
        float sc = 5.656854249f / fmaxf(sqrtf(ss), 1e-12f);
        #pragma unroll
        for (int d = 0; d < DIM_HEAD; d++) qs[t][d] *= sc * qg[d];
    } else if (t >= 128 && t < 128 + NTOK) {
        int r = t - 128;
        float ss = 0.f;
        #pragma unroll
        for (int d = 0; d < DIM_HEAD; d++) { float v = ks[r][d]; ss += v * v; }
        float sc = 5.656854249f / fmaxf(sqrtf(ss), 1e-12f);
        #pragma unroll
        for (int d = 0; d < DIM_HEAD; d++) ks[r][d] *= sc * kg[d];
    }
    __syncthreads();
    for (int e = t; e < NTOK * NTOK; e += 256) {
        int i = e / NTOK, j = e - i * NTOK;
        float s = 0.f;
        #pragma unroll
        for (int d = 0; d < DIM_HEAD; d++) s = fmaf(qs[i][d], ks[j][d], s);
        ps[i][j] = s + rel_emb[rel_idx[e] * HEADS + h];
    }
    __syncthreads();
    if (t < NTOK) {
        float mx = -1e30f;
        #pragma unroll 5
        for (int j = 0; j < NTOK; j++) mx = fmaxf(mx, ps[t][j]);
        float sum = 0.f;
        #pragma unroll 5
        for (int j = 0; j < NTOK; j++) { float p = __expf(ps[t][j] - mx); ps[t][j] = p; sum += p; }
        float inv = 1.f / sum;
        #pragma unroll 5
        for (int j = 0; j < NTOK; j++) ps[t][j] *= inv;
    }
    __syncthreads();
    __half* outp = g_oh + (size_t)(b * NTOK) * DIMX + h * DIM_HEAD;
    for (int e = t; e < NTOK * DIM_HEAD; e += 256) {
        int i = e >> 5, d = e & 31;
        float a = 0.f;
        #pragma unroll 5
        for (int j = 0; j < NTOK; j++) a = fmaf(ps[i][j], vs[j][d], a);
        outp[(size_t)i * DIMX + d] = __float2half_rn(a);
    }
}

extern "C" void kernel_launch(void* const* d_in, const int* in_sizes, int n_in,
                              void* d_out, int out_size)
{
    const float* x       = (const float*)d_in[0];
    const float* cond    = (const float*)d_in[1];
    const float* fw1     = (const float*)d_in[2];
    const float* fb1     = (const float*)d_in[3];
    const float* fw2     = (const float*)d_in[4];
    const float* fb2     = (const float*)d_in[5];
    const float* wqkv    = (const float*)d_in[6];
    const float* qg      = (const float*)d_in[7];
    const float* kg      = (const float*)d_in[8];
    const float* rel_emb = (const float*)d_in[9];
    const float* wout    = (const float*)d_in[10];
    const int*   rel_idx = (const int*)d_in[11];
    float* out = (float*)d_out;

    __half *p_xnh, *p_oh, *p_wqkvT, *p_woutT;
    float *p_qkv;
    cudaGetSymbolAddress((void**)&p_xnh,   g_xnh);
    cudaGetSymbolAddress((void**)&p_qkv,   g_qkv);
    cudaGetSymbolAddress((void**)&p_oh,    g_oh);
    cudaGetSymbolAddress((void**)&p_wqkvT, g_wqkvT);
    cudaGetSymbolAddress((void**)&p_woutT, g_woutT);

    cudaFuncSetAttribute(hgemm_kernel, cudaFuncAttributeMaxDynamicSharedMemorySize, HG_SMEM);

    // launch order chosen so hgemm (qkv) is the 4th launch -> gets ncu capture
    film_fused_kernel<<<B_IMG, 256>>>(cond, fw1, fb1, fw2, fb2);
    wtrans_kernel<<<dim3(128, 32), 256>>>(wqkv, wout);
    ln_film_kernel<<<M_TOK, 256>>>(x);

    hgemm_kernel<<<dim3(3 * DIMX / 128, M_TOK / 128), 256, HG_SMEM>>>(
        p_xnh, p_wqkvT, p_qkv, 3 * DIMX, DIMX);

    attn_kernel<<<dim3(B_TOT, HEADS), 256>>>(qg, kg, rel_emb, rel_idx);

    hgemm_kernel<<<dim3(DIMX / 128, M_TOK / 128), 256, HG_SMEM>>>(
        p_oh, p_woutT, out, DIMX, DIMX);
}

// round 7
// speedup vs baseline: 1.5215x; 1.5215x over previous
#include <cuda_runtime.h>
#include <cuda_fp16.h>
#include <math.h>
#include <stdint.h>

#define DIMX 1024
#define COND_DIM 512
#define HEADS 32
#define DIM_HEAD 32
#define NTOK 65
#define B_TOT 512
#define B_IMG 16
#define M_TOK (B_TOT * NTOK)
#define TWO_DIM (2 * DIMX)
#define NN (NTOK * NTOK)

__device__ float  g_gb[B_IMG * TWO_DIM];
__device__ __half g_xnh[(size_t)M_TOK * DIMX];
__device__ float  g_qkv[(size_t)M_TOK * 3 * DIMX];
__device__ __half g_oh[(size_t)M_TOK * DIMX];
__device__ __half g_wqkvT[(size_t)3 * DIMX * DIMX];
__device__ __half g_woutT[(size_t)DIMX * DIMX];
__device__ float  g_bias[HEADS * NN];

#define CPA16(d, s) asm volatile("cp.async.cg.shared.global [%0], [%1], 16;" :: "r"(d), "l"(s) : "memory")
#define CPC()   asm volatile("cp.async.commit_group;" ::: "memory")
#define CPW0()  asm volatile("cp.async.wait_group 0;" ::: "memory")
#define CPW1()  asm volatile("cp.async.wait_group 1;" ::: "memory")

__device__ __forceinline__ uint32_t smem_u32(const void* p) {
    uint32_t a; asm("{ .reg .u64 t; cvta.to.shared.u64 t, %1; cvt.u32.u64 %0, t; }" : "=r"(a) : "l"(p));
    return a;
}
__device__ __forceinline__ void mma_f16(float* d, const uint32_t* a, const uint32_t* b) {
    asm volatile(
        "mma.sync.aligned.m16n8k16.row.col.f32.f16.f16.f32 "
        "{%0,%1,%2,%3}, {%4,%5,%6,%7}, {%8,%9}, {%0,%1,%2,%3};\n"
        : "+f"(d[0]), "+f"(d[1]), "+f"(d[2]), "+f"(d[3])
        : "r"(a[0]), "r"(a[1]), "r"(a[2]), "r"(a[3]), "r"(b[0]), "r"(b[1]));
}

// ---- fused FiLM MLP ----
__global__ __launch_bounds__(256) void film_fused_kernel(
    const float* __restrict__ cond, const float* __restrict__ w1, const float* __restrict__ b1,
    const float* __restrict__ w2, const float* __restrict__ b2)
{
    __shared__ float cs[COND_DIM];
    __shared__ float hs[TWO_DIM];
    const int i = blockIdx.x, t = threadIdx.x;
    for (int k = t; k < COND_DIM; k += 256) cs[k] = cond[i * COND_DIM + k];
    __syncthreads();
    float acc[8];
    #pragma unroll
    for (int p = 0; p < 8; p++) acc[p] = b1[t + p * 256];
    for (int k = 0; k < COND_DIM; k++) {
        float c = cs[k];
        const float* wr = w1 + (size_t)k * TWO_DIM + t;
        #pragma unroll
        for (int p = 0; p < 8; p++) acc[p] = fmaf(c, wr[p * 256], acc[p]);
    }
    #pragma unroll
    for (int p = 0; p < 8; p++) hs[t + p * 256] = acc[p] / (1.f + __expf(-acc[p]));
    __syncthreads();
    #pragma unroll
    for (int p = 0; p < 8; p++) acc[p] = b2[t + p * 256];
    for (int k = 0; k < TWO_DIM; k++) {
        float c = hs[k];
        const float* wr = w2 + (size_t)k * TWO_DIM + t;
        #pragma unroll
        for (int p = 0; p < 8; p++) acc[p] = fmaf(c, wr[p * 256], acc[p]);
    }
    #pragma unroll
    for (int p = 0; p < 8; p++) g_gb[i * TWO_DIM + t + p * 256] = acc[p];
}

// ---- weight transpose f32->half ----
__global__ __launch_bounds__(256) void wtrans_kernel(
    const float* __restrict__ Wq, const float* __restrict__ Wo)
{
    __shared__ float tbuf[32][33];
    int tx = threadIdx.x & 31, ty = threadIdx.x >> 5;
    const float* W;
    __half* WT;
    int N, n0;
    if (blockIdx.x < 96) { W = Wq; WT = g_wqkvT; N = 3 * DIMX; n0 = blockIdx.x * 32; }
    else                 { W = Wo; WT = g_woutT; N = DIMX;     n0 = (blockIdx.x - 96) * 32; }
    int k0 = blockIdx.y * 32;
    #pragma unroll
    for (int r = 0; r < 32; r += 8)
        tbuf[ty + r][tx] = W[(size_t)(k0 + ty + r) * N + n0 + tx];
    __syncthreads();
    #pragma unroll
    for (int r = 0; r < 32; r += 8)
        WT[(size_t)(n0 + ty + r) * DIMX + k0 + tx] = __float2half_rn(tbuf[tx][ty + r]);
}

// ---- LayerNorm + FiLM -> half ----
__global__ __launch_bounds__(256) void ln_film_kernel(const float* __restrict__ x)
{
    int row = blockIdx.x;
    int img = (row / NTOK) >> 5;
    const float4* xr = (const float4*)(x + (size_t)row * DIMX);
    int t = threadIdx.x;
    float4 v = xr[t];
    float s = v.x + v.y + v.z + v.w;
    float ss = v.x*v.x + v.y*v.y + v.z*v.z + v.w*v.w;
    __shared__ float rs_[8], rss[8];
    #pragma unroll
    for (int o = 16; o > 0; o >>= 1) {
        s += __shfl_down_sync(~0u, s, o); ss += __shfl_down_sync(~0u, ss, o);
    }
    int warp = t >> 5, lane = t & 31;
    if (lane == 0) { rs_[warp] = s; rss[warp] = ss; }
    __syncthreads();
    if (warp == 0) {
        s = (lane < 8) ? rs_[lane] : 0.f; ss = (lane < 8) ? rss[lane] : 0.f;
        #pragma unroll
        for (int o = 4; o > 0; o >>= 1) {
            s += __shfl_down_sync(~0u, s, o); ss += __shfl_down_sync(~0u, ss, o);
        }
        if (lane == 0) { rs_[0] = s; rss[0] = ss; }
    }
    __syncthreads();
    float mu = rs_[0] * (1.f / DIMX);
    float var = rss[0] * (1.f / DIMX) - mu * mu;
    float rstd = rsqrtf(var + 1e-5f);
    const float4* gam = (const float4*)(g_gb + (size_t)img * TWO_DIM);
    const float4* bet = (const float4*)(g_gb + (size_t)img * TWO_DIM + DIMX);
    float4 gv = gam[t], bv = bet[t];
    __half2 h0 = __floats2half2_rn(fmaf((v.x - mu) * rstd, gv.x, bv.x),
                                   fmaf((v.y - mu) * rstd, gv.y, bv.y));
    __half2 h1 = __floats2half2_rn(fmaf((v.z - mu) * rstd, gv.z, bv.z),
                                   fmaf((v.w - mu) * rstd, gv.w, bv.w));
    ((__half2*)(g_xnh + (size_t)row * DIMX))[t * 2]     = h0;
    ((__half2*)(g_xnh + (size_t)row * DIMX))[t * 2 + 1] = h1;
}

// ---- fp16 GEMM 128x128x32, 4-stage cp.async (unchanged from R6) ----
#define ASTR 40
#define TILE_B (128 * ASTR * 2)
#define STG_B (2 * TILE_B)
#define HG_SMEM (4 * STG_B)

__global__ __launch_bounds__(256, 2) void hgemm_kernel(
    const __half* __restrict__ A, const __half* __restrict__ Bt,
    float* __restrict__ C, int N, int K)
{
    extern __shared__ char sm[];
    const uint32_t sb = smem_u32(sm);
    const int tid = threadIdx.x, warp = tid >> 5, lane = tid & 31;
    const int g = lane >> 2, tig = lane & 3;
    const int wm = (warp & 1) * 64, wn = (warp >> 1) * 32;
    const int row0 = blockIdx.y * 128, col0 = blockIdx.x * 128;

    float acc[4][4][4];
    #pragma unroll
    for (int mi = 0; mi < 4; mi++)
        #pragma unroll
        for (int nj = 0; nj < 4; nj++)
            #pragma unroll
            for (int c = 0; c < 4; c++) acc[mi][nj][c] = 0.f;

    const int l_row = tid >> 1;
    const int l_kc0 = (tid & 1) * 2;
    const __half* Ag = A + (size_t)(row0 + l_row) * K + l_kc0 * 8;
    const __half* Bg = Bt + (size_t)(col0 + l_row) * K + l_kc0 * 8;
    const uint32_t sAd = sb + l_row * 80 + l_kc0 * 16;
    const uint32_t sBd = sAd + TILE_B;

    const int KITERS = K >> 5;
    #pragma unroll
    for (int s = 0; s < 2; s++) {
        #pragma unroll
        for (int p = 0; p < 2; p++) {
            CPA16(sAd + s * STG_B + p * 16, Ag + s * 32 + p * 8);
            CPA16(sBd + s * STG_B + p * 16, Bg + s * 32 + p * 8);
        }
        CPC();
    }
    for (int kt = 0; kt < KITERS; kt++) {
        if (kt >= KITERS - 2) { CPW0(); } else { CPW1(); }
        __syncthreads();
        if (kt + 2 < KITERS) {
            const int s = (kt + 2) & 3;
            const int k0 = (kt + 2) << 5;
            #pragma unroll
            for (int p = 0; p < 2; p++) {
                CPA16(sAd + s * STG_B + p * 16, Ag + k0 + p * 8);
                CPA16(sBd + s * STG_B + p * 16, Bg + k0 + p * 8);
            }
            CPC();
        }
        const uint32_t* swA = (const uint32_t*)(sm + (kt & 3) * STG_B);
        const uint32_t* swB = (const uint32_t*)(sm + (kt & 3) * STG_B + TILE_B);
        #pragma unroll
        for (int kk = 0; kk < 2; kk++) {
            uint32_t af[4][4], bf[4][2];
            const int kw = kk * 8 + tig;
            #pragma unroll
            for (int mi = 0; mi < 4; mi++) {
                int m = wm + mi * 16 + g;
                af[mi][0] = swA[m * 20 + kw];
                af[mi][1] = swA[(m + 8) * 20 + kw];
                af[mi][2] = swA[m * 20 + kw + 4];
                af[mi][3] = swA[(m + 8) * 20 + kw + 4];
            }
            #pragma unroll
            for (int nj = 0; nj < 4; nj++) {
                int n = wn + nj * 8 + g;
                bf[nj][0] = swB[n * 20 + kw];
                bf[nj][1] = swB[n * 20 + kw + 4];
            }
            #pragma unroll
            for (int mi = 0; mi < 4; mi++)
                #pragma unroll
                for (int nj = 0; nj < 4; nj++)
                    mma_f16(acc[mi][nj], af[mi], bf[nj]);
        }
        __syncthreads();
    }
    #pragma unroll
    for (int mi = 0; mi < 4; mi++) {
        #pragma unroll
        for (int nj = 0; nj < 4; nj++) {
            int r = row0 + wm + mi * 16 + g;
            int c = col0 + wn + nj * 8 + tig * 2;
            *(float2*)(C + (size_t)r * N + c)       = make_float2(acc[mi][nj][0], acc[mi][nj][1]);
            *(float2*)(C + (size_t)(r + 8) * N + c) = make_float2(acc[mi][nj][2], acc[mi][nj][3]);
        }
    }
}

// ---- bias table: g_bias[h][i*65+j] = rel_emb[rel_idx[i*65+j]*HEADS + h] ----
__global__ __launch_bounds__(256) void bias_kernel(
    const float* __restrict__ rel_emb, const int* __restrict__ rel_idx)
{
    int e = blockIdx.x * 256 + threadIdx.x;
    if (e >= NN) return;
    int idx = rel_idx[e];
    const float* re = rel_emb + (size_t)idx * HEADS;
    #pragma unroll
    for (int h = 0; h < HEADS; h++) g_bias[h * NN + e] = re[h];
}

// ---- attention: padded smem (stride 33) -> conflict-free ----
__global__ __launch_bounds__(256) void attn_kernel(
    const float* __restrict__ q_gamma, const float* __restrict__ k_gamma)
{
    int b = blockIdx.x, h = blockIdx.y;
    __shared__ float qs[NTOK][DIM_HEAD + 1], ks[NTOK][DIM_HEAD + 1], vs[NTOK][DIM_HEAD + 1];
    __shared__ float ps[NTOK][NTOK + 1], qg[DIM_HEAD], kg[DIM_HEAD];
    int t = threadIdx.x;
    if (t < DIM_HEAD) { qg[t] = q_gamma[h * DIM_HEAD + t]; kg[t] = k_gamma[h * DIM_HEAD + t]; }
    const float* base = g_qkv + (size_t)(b * NTOK) * (3 * DIMX) + h * DIM_HEAD;
    for (int e = t; e < NTOK * DIM_HEAD; e += 256) {
        int n = e >> 5, d = e & 31;
        const float* r = base + (size_t)n * (3 * DIMX);
        qs[n][d] = r[d]; ks[n][d] = r[DIMX + d]; vs[n][d] = r[2 * DIMX + d];
    }
    __syncthreads();
    if (t < NTOK) {
        float ss = 0.f;
        #pragma unroll
        for (int d = 0; d < DIM_HEAD; d++) { float v = qs[t][d]; ss += v * v; }
        float sc = 5.656854249f / fmaxf(sqrtf(ss), 1e-12f);
        #pragma unroll
        for (int d = 0; d < DIM_HEAD; d++) qs[t][d] *= sc * qg[d];
    } else if (t >= 128 && t < 128 + NTOK) {
        int r = t - 128;
        float ss = 0.f;
        #pragma unroll
        for (int d = 0; d < DIM_HEAD; d++) { float v = ks[r][d]; ss += v * v; }
        float sc = 5.656854249f / fmaxf(sqrtf(ss), 1e-12f);
        #pragma unroll
        for (int d = 0; d < DIM_HEAD; d++) ks[r][d] *= sc * kg[d];
    }
    __syncthreads();
    const float* bias = g_bias + (size_t)h * NN;
    for (int e = t; e < NN; e += 256) {
        int i = e / NTOK, j = e - i * NTOK;
        float s = 0.f;
        #pragma unroll
        for (int d = 0; d < DIM_HEAD; d++) s = fmaf(qs[i][d], ks[j][d], s);
        ps[i][j] = s + bias[e];
    }
    __syncthreads();
    if (t < NTOK) {
        float mx = -1e30f;
        #pragma unroll 5
        for (int j = 0; j < NTOK; j++) mx = fmaxf(mx, ps[t][j]);
        float sum = 0.f;
        #pragma unroll 5
        for (int j = 0; j < NTOK; j++) { float p = __expf(ps[t][j] - mx); ps[t][j] = p; sum += p; }
        float inv = 1.f / sum;
        #pragma unroll 5
        for (int j = 0; j < NTOK; j++) ps[t][j] *= inv;
    }
    __syncthreads();
    __half* outp = g_oh + (size_t)(b * NTOK) * DIMX + h * DIM_HEAD;
    for (int e = t; e < NTOK * DIM_HEAD; e += 256) {
        int i = e >> 5, d = e & 31;
        float a = 0.f;
        #pragma unroll 5
        for (int j = 0; j < NTOK; j++) a = fmaf(ps[i][j], vs[j][d], a);
        outp[(size_t)i * DIMX + d] = __float2half_rn(a);
    }
}

extern "C" void kernel_launch(void* const* d_in, const int* in_sizes, int n_in,
                              void* d_out, int out_size)
{
    const float* x       = (const float*)d_in[0];
    const float* cond    = (const float*)d_in[1];
    const float* fw1     = (const float*)d_in[2];
    const float* fb1     = (const float*)d_in[3];
    const float* fw2     = (const float*)d_in[4];
    const float* fb2     = (const float*)d_in[5];
    const float* wqkv    = (const float*)d_in[6];
    const float* qg      = (const float*)d_in[7];
    const float* kg      = (const float*)d_in[8];
    const float* rel_emb = (const float*)d_in[9];
    const float* wout    = (const float*)d_in[10];
    const int*   rel_idx = (const int*)d_in[11];
    float* out = (float*)d_out;

    __half *p_xnh, *p_oh, *p_wqkvT, *p_woutT;
    float *p_qkv;
    cudaGetSymbolAddress((void**)&p_xnh,   g_xnh);
    cudaGetSymbolAddress((void**)&p_qkv,   g_qkv);
    cudaGetSymbolAddress((void**)&p_oh,    g_oh);
    cudaGetSymbolAddress((void**)&p_wqkvT, g_wqkvT);
    cudaGetSymbolAddress((void**)&p_woutT, g_woutT);

    cudaFuncSetAttribute(hgemm_kernel, cudaFuncAttributeMaxDynamicSharedMemorySize, HG_SMEM);

    film_fused_kernel<<<B_IMG, 256>>>(cond, fw1, fb1, fw2, fb2);
    wtrans_kernel<<<dim3(128, 32), 256>>>(wqkv, wout);
    ln_film_kernel<<<M_TOK, 256>>>(x);

    // 4th launch -> ncu capture stays on the qkv GEMM
    hgemm_kernel<<<dim3(3 * DIMX / 128, M_TOK / 128), 256, HG_SMEM>>>(
        p_xnh, p_wqkvT, p_qkv, 3 * DIMX, DIMX);

    bias_kernel<<<(NN + 255) / 256, 256>>>(rel_emb, rel_idx);
    attn_kernel<<<dim3(B_TOT, HEADS), 256>>>(qg, kg);

    hgemm_kernel<<<dim3(DIMX / 128, M_TOK / 128), 256, HG_SMEM>>>(
        p_oh, p_woutT, out, DIMX, DIMX);
}